// round 3
// baseline (speedup 1.0000x reference)
#include <cuda_runtime.h>
#include <math.h>

#define B   16
#define T   12
#define NN  2048
#define FI  32
#define FO  64
#define KC  3

// ---------------- static scratch (no allocations allowed) ----------------
__device__ float g_qt[(size_t)B*T*NN];
__device__ float g_kt[(size_t)B*T*NN];
__device__ float g_ta[(size_t)B*T*T];
__device__ __align__(16) float g_xta[(size_t)B*T*NN*FI];
__device__ __align__(16) float g_qs[(size_t)B*NN*T];   // (B,N,T) transposed
__device__ __align__(16) float g_ks[(size_t)B*NN*T];   // (B,N,T) transposed
__device__ __align__(16) float g_sa[(size_t)B*NN*NN];
__device__ __align__(16) float g_xgc[(size_t)B*T*NN*FO];

// ---------------- K1: qt/kt = x @ wq_t / wk_t ----------------
__global__ void k1_qk(const float* __restrict__ x,
                      const float* __restrict__ wq, const float* __restrict__ wk)
{
    __shared__ float sw[64];
    int tid = threadIdx.x;
    if (tid < 64) sw[tid] = (tid < 32) ? wq[tid] : wk[tid - 32];
    __syncthreads();
    size_t g = (size_t)blockIdx.x * 256 + tid;       // < B*T*NN
    const float4* xr = (const float4*)(x + g * FI);
    float aq = 0.f, ak = 0.f;
#pragma unroll
    for (int u = 0; u < 8; u++) {
        float4 v = xr[u];
        aq += v.x*sw[u*4+0] + v.y*sw[u*4+1] + v.z*sw[u*4+2] + v.w*sw[u*4+3];
        ak += v.x*sw[32+u*4+0] + v.y*sw[32+u*4+1] + v.z*sw[32+u*4+2] + v.w*sw[32+u*4+3];
    }
    g_qt[g] = aq; g_kt[g] = ak;
}

// ---------------- K2: temporal attention ta (B,T,T), softmax over s ----------------
__global__ void k2_ta()
{
    int b = blockIdx.x / T, t = blockIdx.x % T;
    int tid = threadIdx.x;
    const float* q  = g_qt + ((size_t)b*T + t) * NN;
    const float* kb = g_kt + (size_t)b*T*NN;
    float p[T];
#pragma unroll
    for (int s = 0; s < T; s++) p[s] = 0.f;
    for (int n = tid; n < NN; n += 256) {
        float qv = q[n];
#pragma unroll
        for (int s = 0; s < T; s++) p[s] += qv * kb[(size_t)s*NN + n];
    }
    __shared__ float sc[T];
    if (tid < T) sc[tid] = 0.f;
    __syncthreads();
#pragma unroll
    for (int s = 0; s < T; s++) {
        float v = p[s];
        for (int off = 16; off; off >>= 1) v += __shfl_down_sync(0xffffffffu, v, off);
        if ((tid & 31) == 0) atomicAdd(&sc[s], v);
    }
    __syncthreads();
    if (tid == 0) {
        const float isN = 0.022097086912079612f;   // 1/sqrt(2048)
        float sv[T], mx = -1e30f;
#pragma unroll
        for (int s = 0; s < T; s++) { sv[s] = sc[s]*isN; mx = fmaxf(mx, sv[s]); }
        float sum = 0.f;
#pragma unroll
        for (int s = 0; s < T; s++) { sv[s] = __expf(sv[s]-mx); sum += sv[s]; }
        float inv = 1.f / sum;
        float* out = g_ta + ((size_t)b*T + t) * T;
#pragma unroll
        for (int s = 0; s < T; s++) out[s] = sv[s]*inv;
    }
}

// ---------------- K3: x_ta[b,t,n,f] = sum_s ta[b,t,s] x[b,s,n,f] ----------------
__global__ __launch_bounds__(1024) void k3_xta(const float* __restrict__ x)
{
    __shared__ float tas[T*T];
    int b = blockIdx.y, n0 = blockIdx.x << 5;
    int tid = threadIdx.x;
    if (tid < T*T) tas[tid] = g_ta[(size_t)b*T*T + tid];
    __syncthreads();
    int f = tid & 31, nl = tid >> 5;
    size_t base = ((size_t)b*T*NN + (n0 + nl)) * FI + f;
    float v[T];
#pragma unroll
    for (int s = 0; s < T; s++) v[s] = x[base + (size_t)s*NN*FI];
#pragma unroll
    for (int t = 0; t < T; t++) {
        float a = 0.f;
#pragma unroll
        for (int s = 0; s < T; s++) a += tas[t*T + s] * v[s];
        g_xta[base + (size_t)t*NN*FI] = a;
    }
}

// ---------------- K4: qs/ks from x_ta, stored (B,N,T) transposed ----------------
__global__ void k4_qk(const float* __restrict__ wq, const float* __restrict__ wk)
{
    __shared__ float sw[64];
    int tid = threadIdx.x;
    if (tid < 64) sw[tid] = (tid < 32) ? wq[tid] : wk[tid - 32];
    __syncthreads();
    size_t g = (size_t)blockIdx.x * 256 + tid;
    const float4* xr = (const float4*)(g_xta + g * FI);
    float aq = 0.f, ak = 0.f;
#pragma unroll
    for (int u = 0; u < 8; u++) {
        float4 v = xr[u];
        aq += v.x*sw[u*4+0] + v.y*sw[u*4+1] + v.z*sw[u*4+2] + v.w*sw[u*4+3];
        ak += v.x*sw[32+u*4+0] + v.y*sw[32+u*4+1] + v.z*sw[32+u*4+2] + v.w*sw[32+u*4+3];
    }
    int n = (int)(g % NN);
    size_t bt = g / NN;
    int t = (int)(bt % T);
    int b = (int)(bt / T);
    size_t o = ((size_t)b*NN + n) * T + t;
    g_qs[o] = aq; g_ks[o] = ak;
}

// ---------------- K5: spatial attention sa (B,N,N), softmax over m ----------------
__global__ __launch_bounds__(256) void k5_sa()
{
    __shared__ float buf[NN];
    __shared__ float red[256];
    __shared__ float qr[T];
    int b = blockIdx.x >> 11;
    int i = blockIdx.x & (NN - 1);
    int tid = threadIdx.x;
    const float* qsb = g_qs + ((size_t)b*NN + i) * T;
    const float* ksb = g_ks + (size_t)b*NN*T;
    if (tid < T) qr[tid] = qsb[tid];
    __syncthreads();
    const float isT = 0.28867513459481287f;   // 1/sqrt(12)
    float lmax = -1e30f;
    for (int m = tid; m < NN; m += 256) {
        const float4* kr = (const float4*)(ksb + (size_t)m * T);
        float4 A = kr[0], Bv = kr[1], C = kr[2];
        float s = qr[0]*A.x + qr[1]*A.y + qr[2]*A.z + qr[3]*A.w
                + qr[4]*Bv.x + qr[5]*Bv.y + qr[6]*Bv.z + qr[7]*Bv.w
                + qr[8]*C.x + qr[9]*C.y + qr[10]*C.z + qr[11]*C.w;
        s *= isT;
        buf[m] = s;
        lmax = fmaxf(lmax, s);
    }
    red[tid] = lmax; __syncthreads();
    for (int s = 128; s > 0; s >>= 1) { if (tid < s) red[tid] = fmaxf(red[tid], red[tid+s]); __syncthreads(); }
    float mx = red[0]; __syncthreads();
    float lsum = 0.f;
    for (int m = tid; m < NN; m += 256) { float e = __expf(buf[m]-mx); buf[m] = e; lsum += e; }
    red[tid] = lsum; __syncthreads();
    for (int s = 128; s > 0; s >>= 1) { if (tid < s) red[tid] += red[tid+s]; __syncthreads(); }
    float inv = 1.f / red[0];
    float* out = g_sa + ((size_t)b*NN + i) * NN;
    for (int m = tid; m < NN; m += 256) out[m] = buf[m] * inv;
}

// ---------------- K6: fused Chebyshev GEMM + theta epilogue + relu ----------------
#define BM6 128
#define BN6 64
#define BK6 16

__global__ __launch_bounds__(256) void k6_cheb_gemm(const float* __restrict__ cheb,
                                                    const float* __restrict__ theta)
{
    __shared__ float sp[10240];   // mainloop: As[3][16][128] + Bs[16][64]; epilogue: Cs[128][64] + th[1024]
    const int b  = blockIdx.z;
    const int i0 = blockIdx.y * BM6;
    const int c0 = blockIdx.x * BN6;
    const int t0 = c0 >> 5;
    const int tid = threadIdx.x;
    const int tx = tid & 15, ty = tid >> 4;

    const float* sab = g_sa  + (size_t)b * NN * NN;
    const float* xb  = g_xta + (size_t)b * T * NN * FI;

    float acc[3][8][4];
#pragma unroll
    for (int k = 0; k < 3; k++)
#pragma unroll
        for (int r = 0; r < 8; r++)
#pragma unroll
            for (int c = 0; c < 4; c++) acc[k][r][c] = 0.f;

    float* Bs = sp + 3*BK6*BM6;   // offset 6144

    for (int j0 = 0; j0 < NN; j0 += BK6) {
        // B tile: x_ta[b, t0+tt, j0+jj, f]
        {
            int jj = tid >> 4, q = tid & 15;
            int tt = q >> 3, f = (q & 7) << 2;
            float4 v = *(const float4*)(xb + ((size_t)(t0+tt)*NN + (j0+jj)) * FI + f);
            *(float4*)(Bs + jj*BN6 + (q << 2)) = v;
        }
        // A tiles: (cheb_k * sa), stored transposed [k][jj][i]
#pragma unroll
        for (int u = 0; u < 2; u++) {
            int idx = (tid << 1) + u;         // 0..511
            int row = idx >> 2, q = idx & 3;
            size_t off = (size_t)(i0 + row) * NN + j0 + (q << 2);
            float4 s4 = *(const float4*)(sab + off);
#pragma unroll
            for (int k = 0; k < 3; k++) {
                float4 c4 = *(const float4*)(cheb + (size_t)k*NN*NN + off);
                float* As = sp + k*(BK6*BM6);
                As[(q*4+0)*BM6 + row] = c4.x * s4.x;
                As[(q*4+1)*BM6 + row] = c4.y * s4.y;
                As[(q*4+2)*BM6 + row] = c4.z * s4.z;
                As[(q*4+3)*BM6 + row] = c4.w * s4.w;
            }
        }
        __syncthreads();
#pragma unroll
        for (int jj = 0; jj < BK6; jj++) {
            float4 bv = *(const float4*)(Bs + jj*BN6 + (tx << 2));
#pragma unroll
            for (int k = 0; k < 3; k++) {
                const float* Ar = sp + k*(BK6*BM6) + jj*BM6 + (ty << 3);
                float4 a0 = *(const float4*)(Ar);
                float4 a1 = *(const float4*)(Ar + 4);
                float av[8] = {a0.x,a0.y,a0.z,a0.w,a1.x,a1.y,a1.z,a1.w};
#pragma unroll
                for (int r = 0; r < 8; r++) {
                    acc[k][r][0] += av[r]*bv.x;
                    acc[k][r][1] += av[r]*bv.y;
                    acc[k][r][2] += av[r]*bv.z;
                    acc[k][r][3] += av[r]*bv.w;
                }
            }
        }
        __syncthreads();
    }

    // epilogue: xgc[b, t0+tt, i, o] = relu( sum_k sum_f Cs_k[i, tt*32+f] * theta[k,f,o] )
    float* Cs = sp;            // 8192 floats
    float* th = sp + 8192;     // 1024 used
    const int og = tid & 31, gg = tid >> 5;

#pragma unroll
    for (int h = 0; h < 2; h++) {
        float o32[16][2];
#pragma unroll
        for (int rr = 0; rr < 16; rr++) { o32[rr][0] = 0.f; o32[rr][1] = 0.f; }
#pragma unroll
        for (int k = 0; k < 3; k++) {
            __syncthreads();
#pragma unroll
            for (int r = 0; r < 8; r++)
#pragma unroll
                for (int c = 0; c < 4; c++)
                    Cs[(ty*8+r)*BN6 + tx*4 + c] = acc[k][r][c];
#pragma unroll
            for (int u = 0; u < 4; u++) {
                int id = tid + 256*u;          // 0..1023
                int f = id >> 5, oo = id & 31;
                th[id] = theta[k*(FI*FO) + f*FO + h*32 + oo];
            }
            __syncthreads();
#pragma unroll
            for (int rr = 0; rr < 16; rr++) {
                int i = gg + (rr << 3);
#pragma unroll
                for (int tt = 0; tt < 2; tt++) {
                    const float* cr = Cs + i*BN6 + tt*32;
                    float a = 0.f;
#pragma unroll
                    for (int f = 0; f < 32; f++) a += cr[f] * th[f*32 + og];
                    o32[rr][tt] += a;
                }
            }
        }
#pragma unroll
        for (int rr = 0; rr < 16; rr++) {
            int i = i0 + gg + (rr << 3);
#pragma unroll
            for (int tt = 0; tt < 2; tt++) {
                float v = o32[rr][tt];
                v = v > 0.f ? v : 0.f;
                g_xgc[(((size_t)b*T + (t0+tt))*NN + i)*FO + h*32 + og] = v;
            }
        }
    }
}

// ---------------- K7: temporal conv + residual conv + relu + layernorm ----------------
// smem: Ws[224][68] fused (tconv 192 + rconv 32 rows) | xg[3][32][64] | xr[32][32] | yb[32][65] | mu/ri
#define S7_WS   0
#define S7_XG   15232
#define S7_XR   (S7_XG + 6144)
#define S7_YB   (S7_XR + 1024)
#define S7_MU   (S7_YB + 2080)
#define S7_RI   (S7_MU + 32)
#define S7_TOTF (S7_RI + 32)       // 24544 floats = 98176 bytes

__global__ __launch_bounds__(256) void k7_final(
    const float* __restrict__ x,
    const float* __restrict__ tw, const float* __restrict__ tb,
    const float* __restrict__ rw, const float* __restrict__ rb,
    const float* __restrict__ lg, const float* __restrict__ lb,
    float* __restrict__ out)
{
    extern __shared__ float s7[];
    float* Ws = s7 + S7_WS;
    float* xg = s7 + S7_XG;
    float* xr = s7 + S7_XR;
    float* yb = s7 + S7_YB;
    float* mu = s7 + S7_MU;
    float* ri = s7 + S7_RI;

    int b = blockIdx.z, t = blockIdx.y, n0 = blockIdx.x << 5;
    int tid = threadIdx.x;

    for (int idx = tid; idx < FO*192; idx += 256) { int o = idx / 192, r = idx - o*192; Ws[r*68 + o] = tw[idx]; }
    for (int idx = tid; idx < FO*FI; idx += 256) { int o = idx >> 5, f = idx & 31; Ws[(192+f)*68 + o] = rw[idx]; }
#pragma unroll
    for (int dt = 0; dt < 3; dt++) {
        int ts = t + dt - 1;
        if (ts >= 0 && ts < T) {
            const float* src = g_xgc + (((size_t)b*T + ts)*NN + n0) * FO;
            for (int idx = tid; idx < 32*FO; idx += 256) xg[dt*2048 + idx] = src[idx];
        } else {
            for (int idx = tid; idx < 32*FO; idx += 256) xg[dt*2048 + idx] = 0.f;
        }
    }
    {
        const float* src = x + (((size_t)b*T + t)*NN + n0) * FI;
        for (int idx = tid; idx < 32*FI; idx += 256) xr[idx] = src[idx];
    }
    __syncthreads();

    int og = tid & 15, nlg = tid >> 4;
    int o0 = og << 2, nl0 = nlg << 1;
    float4 tb4 = *(const float4*)(tb + o0);
    float4 rb4 = *(const float4*)(rb + o0);
    float acc0[4], acc1[4];
#pragma unroll
    for (int c = 0; c < 4; c++) {
        float bia = ((const float*)&tb4)[c] + ((const float*)&rb4)[c];
        acc0[c] = bia; acc1[c] = bia;
    }

    for (int c = 0; c < FO; c++) {
#pragma unroll
        for (int dt = 0; dt < 3; dt++) {
            float4 w = *(const float4*)(Ws + (c*3 + dt)*68 + o0);
            float xa = xg[dt*2048 + nl0*FO + c];
            float xb2 = xg[dt*2048 + nl0*FO + FO + c];
            acc0[0] += xa*w.x;  acc0[1] += xa*w.y;  acc0[2] += xa*w.z;  acc0[3] += xa*w.w;
            acc1[0] += xb2*w.x; acc1[1] += xb2*w.y; acc1[2] += xb2*w.z; acc1[3] += xb2*w.w;
        }
    }
#pragma unroll
    for (int f = 0; f < FI; f++) {
        float4 w = *(const float4*)(Ws + (192 + f)*68 + o0);
        float xa = xr[nl0*FI + f];
        float xb2 = xr[nl0*FI + FI + f];
        acc0[0] += xa*w.x;  acc0[1] += xa*w.y;  acc0[2] += xa*w.z;  acc0[3] += xa*w.w;
        acc1[0] += xb2*w.x; acc1[1] += xb2*w.y; acc1[2] += xb2*w.z; acc1[3] += xb2*w.w;
    }
#pragma unroll
    for (int c = 0; c < 4; c++) {
        float v0 = acc0[c] > 0.f ? acc0[c] : 0.f;
        float v1 = acc1[c] > 0.f ? acc1[c] : 0.f;
        yb[nl0*65 + o0 + c] = v0;
        yb[(nl0+1)*65 + o0 + c] = v1;
    }
    __syncthreads();
    if (tid < 32) {
        float m = 0.f;
#pragma unroll
        for (int o = 0; o < FO; o++) m += yb[tid*65 + o];
        m *= (1.f/FO);
        float v = 0.f;
#pragma unroll
        for (int o = 0; o < FO; o++) { float d = yb[tid*65 + o] - m; v += d*d; }
        v *= (1.f/FO);
        mu[tid] = m;
        ri[tid] = rsqrtf(v + 1e-5f);
    }
    __syncthreads();
    float4 g4 = *(const float4*)(lg + o0);
    float4 b4 = *(const float4*)(lb + o0);
#pragma unroll
    for (int j = 0; j < 2; j++) {
        int nl = nl0 + j;
        float m = mu[nl], r = ri[nl];
        float4 ov;
        ov.x = (yb[nl*65 + o0 + 0] - m)*r*g4.x + b4.x;
        ov.y = (yb[nl*65 + o0 + 1] - m)*r*g4.y + b4.y;
        ov.z = (yb[nl*65 + o0 + 2] - m)*r*g4.z + b4.z;
        ov.w = (yb[nl*65 + o0 + 3] - m)*r*g4.w + b4.w;
        *(float4*)(out + ((((size_t)b*T + t)*NN + n0 + nl) << 6) + o0) = ov;
    }
}

// ---------------- launch ----------------
extern "C" void kernel_launch(void* const* d_in, const int* in_sizes, int n_in,
                              void* d_out, int out_size)
{
    const float* x     = (const float*)d_in[0];
    const float* cheb  = (const float*)d_in[1];
    const float* wq_t  = (const float*)d_in[2];
    const float* wk_t  = (const float*)d_in[3];
    const float* wq_s  = (const float*)d_in[4];
    const float* wk_s  = (const float*)d_in[5];
    const float* theta = (const float*)d_in[6];
    const float* tw    = (const float*)d_in[7];
    const float* tbv   = (const float*)d_in[8];
    const float* rw    = (const float*)d_in[9];
    const float* rbv   = (const float*)d_in[10];
    const float* lg    = (const float*)d_in[11];
    const float* lb    = (const float*)d_in[12];
    float* out = (float*)d_out;

    cudaFuncSetAttribute(k7_final, cudaFuncAttributeMaxDynamicSharedMemorySize,
                         S7_TOTF * (int)sizeof(float));

    k1_qk<<<(B*T*NN)/256, 256>>>(x, wq_t, wk_t);
    k2_ta<<<B*T, 256>>>();
    k3_xta<<<dim3(NN/32, B), 1024>>>(x);
    k4_qk<<<(B*T*NN)/256, 256>>>(wq_s, wk_s);
    k5_sa<<<B*NN, 256>>>();
    k6_cheb_gemm<<<dim3((T*FI)/BN6, NN/BM6, B), 256>>>(cheb, theta);
    k7_final<<<dim3(NN/32, T, B), 256, S7_TOTF * (int)sizeof(float)>>>(
        x, tw, tbv, rw, rbv, lg, lb, out);
}

// round 4
// speedup vs baseline: 1.0418x; 1.0418x over previous
#include <cuda_runtime.h>
#include <math.h>

#define B   16
#define T   12
#define NN  2048
#define FI  32
#define FO  64
#define KC  3

typedef unsigned long long ull;

// ---------------- static scratch (no allocations allowed) ----------------
__device__ float g_qt[(size_t)B*T*NN];
__device__ float g_kt[(size_t)B*T*NN];
__device__ float g_ta[(size_t)B*T*T];
__device__ __align__(16) float g_xta[(size_t)B*T*NN*FI];
__device__ __align__(16) float g_qs[(size_t)B*NN*T];   // (B,N,T) transposed
__device__ __align__(16) float g_ks[(size_t)B*NN*T];   // (B,N,T) transposed
__device__ __align__(16) float g_sa[(size_t)B*NN*NN];
__device__ __align__(16) float g_xgc[(size_t)B*T*NN*FO];

// packed f32x2 helpers (sm_103a FFMA2 — ptxas only emits via explicit PTX)
__device__ __forceinline__ void ffma2(ull& d, ull a, ull b) {
    asm("fma.rn.f32x2 %0, %1, %2, %0;" : "+l"(d) : "l"(a), "l"(b));
}
__device__ __forceinline__ ull rep2(float v) {
    ull r; unsigned u = __float_as_uint(v);
    asm("mov.b64 %0, {%1, %1};" : "=l"(r) : "r"(u));
    return r;
}
union F4U { float4 f; ull u[2]; };
union U2F { ull u; float f[2]; };

// ---------------- K1: qt/kt = x @ wq_t / wk_t ----------------
__global__ void k1_qk(const float* __restrict__ x,
                      const float* __restrict__ wq, const float* __restrict__ wk)
{
    __shared__ float sw[64];
    int tid = threadIdx.x;
    if (tid < 64) sw[tid] = (tid < 32) ? wq[tid] : wk[tid - 32];
    __syncthreads();
    size_t g = (size_t)blockIdx.x * 256 + tid;       // < B*T*NN
    const float4* xr = (const float4*)(x + g * FI);
    float aq = 0.f, ak = 0.f;
#pragma unroll
    for (int u = 0; u < 8; u++) {
        float4 v = xr[u];
        aq += v.x*sw[u*4+0] + v.y*sw[u*4+1] + v.z*sw[u*4+2] + v.w*sw[u*4+3];
        ak += v.x*sw[32+u*4+0] + v.y*sw[32+u*4+1] + v.z*sw[32+u*4+2] + v.w*sw[32+u*4+3];
    }
    g_qt[g] = aq; g_kt[g] = ak;
}

// ---------------- K2: temporal attention ta (B,T,T), softmax over s ----------------
__global__ void k2_ta()
{
    int b = blockIdx.x / T, t = blockIdx.x % T;
    int tid = threadIdx.x;
    const float* q  = g_qt + ((size_t)b*T + t) * NN;
    const float* kb = g_kt + (size_t)b*T*NN;
    float p[T];
#pragma unroll
    for (int s = 0; s < T; s++) p[s] = 0.f;
    for (int n = tid; n < NN; n += 256) {
        float qv = q[n];
#pragma unroll
        for (int s = 0; s < T; s++) p[s] += qv * kb[(size_t)s*NN + n];
    }
    __shared__ float sc[T];
    if (tid < T) sc[tid] = 0.f;
    __syncthreads();
#pragma unroll
    for (int s = 0; s < T; s++) {
        float v = p[s];
        for (int off = 16; off; off >>= 1) v += __shfl_down_sync(0xffffffffu, v, off);
        if ((tid & 31) == 0) atomicAdd(&sc[s], v);
    }
    __syncthreads();
    if (tid == 0) {
        const float isN = 0.022097086912079612f;   // 1/sqrt(2048)
        float sv[T], mx = -1e30f;
#pragma unroll
        for (int s = 0; s < T; s++) { sv[s] = sc[s]*isN; mx = fmaxf(mx, sv[s]); }
        float sum = 0.f;
#pragma unroll
        for (int s = 0; s < T; s++) { sv[s] = __expf(sv[s]-mx); sum += sv[s]; }
        float inv = 1.f / sum;
        float* out = g_ta + ((size_t)b*T + t) * T;
#pragma unroll
        for (int s = 0; s < T; s++) out[s] = sv[s]*inv;
    }
}

// ---------------- K3: x_ta[b,t,n,f] = sum_s ta[b,t,s] x[b,s,n,f] ----------------
__global__ __launch_bounds__(1024) void k3_xta(const float* __restrict__ x)
{
    __shared__ float tas[T*T];
    int b = blockIdx.y, n0 = blockIdx.x << 5;
    int tid = threadIdx.x;
    if (tid < T*T) tas[tid] = g_ta[(size_t)b*T*T + tid];
    __syncthreads();
    int f = tid & 31, nl = tid >> 5;
    size_t base = ((size_t)b*T*NN + (n0 + nl)) * FI + f;
    float v[T];
#pragma unroll
    for (int s = 0; s < T; s++) v[s] = x[base + (size_t)s*NN*FI];
#pragma unroll
    for (int t = 0; t < T; t++) {
        float a = 0.f;
#pragma unroll
        for (int s = 0; s < T; s++) a += tas[t*T + s] * v[s];
        g_xta[base + (size_t)t*NN*FI] = a;
    }
}

// ---------------- K4: qs/ks from x_ta, stored (B,N,T) transposed ----------------
__global__ void k4_qk(const float* __restrict__ wq, const float* __restrict__ wk)
{
    __shared__ float sw[64];
    int tid = threadIdx.x;
    if (tid < 64) sw[tid] = (tid < 32) ? wq[tid] : wk[tid - 32];
    __syncthreads();
    size_t g = (size_t)blockIdx.x * 256 + tid;
    const float4* xr = (const float4*)(g_xta + g * FI);
    float aq = 0.f, ak = 0.f;
#pragma unroll
    for (int u = 0; u < 8; u++) {
        float4 v = xr[u];
        aq += v.x*sw[u*4+0] + v.y*sw[u*4+1] + v.z*sw[u*4+2] + v.w*sw[u*4+3];
        ak += v.x*sw[32+u*4+0] + v.y*sw[32+u*4+1] + v.z*sw[32+u*4+2] + v.w*sw[32+u*4+3];
    }
    int n = (int)(g % NN);
    size_t bt = g / NN;
    int t = (int)(bt % T);
    int b = (int)(bt / T);
    size_t o = ((size_t)b*NN + n) * T + t;
    g_qs[o] = aq; g_ks[o] = ak;
}

// ---------------- K5: spatial attention sa (B,N,N), softmax over m ----------------
__global__ __launch_bounds__(256) void k5_sa()
{
    __shared__ float buf[NN];
    __shared__ float red[256];
    __shared__ float qr[T];
    int b = blockIdx.x >> 11;
    int i = blockIdx.x & (NN - 1);
    int tid = threadIdx.x;
    const float* qsb = g_qs + ((size_t)b*NN + i) * T;
    const float* ksb = g_ks + (size_t)b*NN*T;
    if (tid < T) qr[tid] = qsb[tid];
    __syncthreads();
    const float isT = 0.28867513459481287f;   // 1/sqrt(12)
    float lmax = -1e30f;
    for (int m = tid; m < NN; m += 256) {
        const float4* kr = (const float4*)(ksb + (size_t)m * T);
        float4 A = kr[0], Bv = kr[1], C = kr[2];
        float s = qr[0]*A.x + qr[1]*A.y + qr[2]*A.z + qr[3]*A.w
                + qr[4]*Bv.x + qr[5]*Bv.y + qr[6]*Bv.z + qr[7]*Bv.w
                + qr[8]*C.x + qr[9]*C.y + qr[10]*C.z + qr[11]*C.w;
        s *= isT;
        buf[m] = s;
        lmax = fmaxf(lmax, s);
    }
    red[tid] = lmax; __syncthreads();
    for (int s = 128; s > 0; s >>= 1) { if (tid < s) red[tid] = fmaxf(red[tid], red[tid+s]); __syncthreads(); }
    float mx = red[0]; __syncthreads();
    float lsum = 0.f;
    for (int m = tid; m < NN; m += 256) { float e = __expf(buf[m]-mx); buf[m] = e; lsum += e; }
    red[tid] = lsum; __syncthreads();
    for (int s = 128; s > 0; s >>= 1) { if (tid < s) red[tid] += red[tid+s]; __syncthreads(); }
    float inv = 1.f / red[0];
    float* out = g_sa + ((size_t)b*NN + i) * NN;
    for (int m = tid; m < NN; m += 256) out[m] = buf[m] * inv;
}

// ---------------- K6: fused Chebyshev GEMM + theta epilogue + relu ----------------
// FFMA2 (fma.rn.f32x2) micro-kernel: accumulator pairs over the row dim,
// A pairs free via LDS.128 reinterpret, B replicated to both lanes via mov.b64.
#define BM6 128
#define BN6 64
#define BK6 16

__global__ __launch_bounds__(256) void k6_cheb_gemm(const float* __restrict__ cheb,
                                                    const float* __restrict__ theta)
{
    __shared__ float sp[10240];   // mainloop: As[3][16][128] + Bs[16][64]; epilogue: Cs[128][64] + th[1024]
    const int b  = blockIdx.z;
    const int i0 = blockIdx.y * BM6;
    const int c0 = blockIdx.x * BN6;
    const int t0 = c0 >> 5;
    const int tid = threadIdx.x;
    const int tx = tid & 15, ty = tid >> 4;

    const float* sab = g_sa  + (size_t)b * NN * NN;
    const float* xb  = g_xta + (size_t)b * T * NN * FI;

    // acc[k][rp][c]: packed pairs over rows (r = 2*rp, 2*rp+1)
    ull acc[3][4][4];
#pragma unroll
    for (int k = 0; k < 3; k++)
#pragma unroll
        for (int rp = 0; rp < 4; rp++)
#pragma unroll
            for (int c = 0; c < 4; c++) acc[k][rp][c] = 0ull;

    float* Bs = sp + 3*BK6*BM6;   // offset 6144

    for (int j0 = 0; j0 < NN; j0 += BK6) {
        // B tile: x_ta[b, t0+tt, j0+jj, f]
        {
            int jj = tid >> 4, q = tid & 15;
            int tt = q >> 3, f = (q & 7) << 2;
            float4 v = *(const float4*)(xb + ((size_t)(t0+tt)*NN + (j0+jj)) * FI + f);
            *(float4*)(Bs + jj*BN6 + (q << 2)) = v;
        }
        // A tiles: (cheb_k * sa), stored transposed [k][jj][i]
#pragma unroll
        for (int u = 0; u < 2; u++) {
            int idx = (tid << 1) + u;         // 0..511
            int row = idx >> 2, q = idx & 3;
            size_t off = (size_t)(i0 + row) * NN + j0 + (q << 2);
            float4 s4 = *(const float4*)(sab + off);
#pragma unroll
            for (int k = 0; k < 3; k++) {
                float4 c4 = *(const float4*)(cheb + (size_t)k*NN*NN + off);
                float* As = sp + k*(BK6*BM6);
                As[(q*4+0)*BM6 + row] = c4.x * s4.x;
                As[(q*4+1)*BM6 + row] = c4.y * s4.y;
                As[(q*4+2)*BM6 + row] = c4.z * s4.z;
                As[(q*4+3)*BM6 + row] = c4.w * s4.w;
            }
        }
        __syncthreads();
#pragma unroll
        for (int jj = 0; jj < BK6; jj++) {
            float4 bv = *(const float4*)(Bs + jj*BN6 + (tx << 2));
            ull br0 = rep2(bv.x), br1 = rep2(bv.y), br2 = rep2(bv.z), br3 = rep2(bv.w);
#pragma unroll
            for (int k = 0; k < 3; k++) {
                const float* Ar = sp + k*(BK6*BM6) + jj*BM6 + (ty << 3);
                F4U a0, a1;
                a0.f = *(const float4*)(Ar);
                a1.f = *(const float4*)(Ar + 4);
                ull ap0 = a0.u[0], ap1 = a0.u[1], ap2 = a1.u[0], ap3 = a1.u[1];
                ffma2(acc[k][0][0], ap0, br0); ffma2(acc[k][0][1], ap0, br1);
                ffma2(acc[k][0][2], ap0, br2); ffma2(acc[k][0][3], ap0, br3);
                ffma2(acc[k][1][0], ap1, br0); ffma2(acc[k][1][1], ap1, br1);
                ffma2(acc[k][1][2], ap1, br2); ffma2(acc[k][1][3], ap1, br3);
                ffma2(acc[k][2][0], ap2, br0); ffma2(acc[k][2][1], ap2, br1);
                ffma2(acc[k][2][2], ap2, br2); ffma2(acc[k][2][3], ap2, br3);
                ffma2(acc[k][3][0], ap3, br0); ffma2(acc[k][3][1], ap3, br1);
                ffma2(acc[k][3][2], ap3, br2); ffma2(acc[k][3][3], ap3, br3);
            }
        }
        __syncthreads();
    }

    // epilogue: xgc[b, t0+tt, i, o] = relu( sum_k sum_f Cs_k[i, tt*32+f] * theta[k,f,o] )
    float* Cs = sp;            // 8192 floats
    float* th = sp + 8192;     // 1024 used
    const int og = tid & 31, gg = tid >> 5;

#pragma unroll
    for (int h = 0; h < 2; h++) {
        float o32[16][2];
#pragma unroll
        for (int rr = 0; rr < 16; rr++) { o32[rr][0] = 0.f; o32[rr][1] = 0.f; }
#pragma unroll
        for (int k = 0; k < 3; k++) {
            __syncthreads();
#pragma unroll
            for (int rp = 0; rp < 4; rp++)
#pragma unroll
                for (int c = 0; c < 4; c++) {
                    U2F v; v.u = acc[k][rp][c];
                    Cs[(ty*8 + 2*rp    )*BN6 + tx*4 + c] = v.f[0];
                    Cs[(ty*8 + 2*rp + 1)*BN6 + tx*4 + c] = v.f[1];
                }
#pragma unroll
            for (int u = 0; u < 4; u++) {
                int id = tid + 256*u;          // 0..1023
                int f = id >> 5, oo = id & 31;
                th[id] = theta[k*(FI*FO) + f*FO + h*32 + oo];
            }
            __syncthreads();
#pragma unroll
            for (int rr = 0; rr < 16; rr++) {
                int i = gg + (rr << 3);
#pragma unroll
                for (int tt = 0; tt < 2; tt++) {
                    const float* cr = Cs + i*BN6 + tt*32;
                    float a = 0.f;
#pragma unroll
                    for (int f = 0; f < 32; f++) a += cr[f] * th[f*32 + og];
                    o32[rr][tt] += a;
                }
            }
        }
#pragma unroll
        for (int rr = 0; rr < 16; rr++) {
            int i = i0 + gg + (rr << 3);
#pragma unroll
            for (int tt = 0; tt < 2; tt++) {
                float v = o32[rr][tt];
                v = v > 0.f ? v : 0.f;
                g_xgc[(((size_t)b*T + (t0+tt))*NN + i)*FO + h*32 + og] = v;
            }
        }
    }
}

// ---------------- K7: temporal conv + residual conv + relu + layernorm ----------------
#define S7_WS   0
#define S7_XG   15232
#define S7_XR   (S7_XG + 6144)
#define S7_YB   (S7_XR + 1024)
#define S7_MU   (S7_YB + 2080)
#define S7_RI   (S7_MU + 32)
#define S7_TOTF (S7_RI + 32)       // 24544 floats = 98176 bytes

__global__ __launch_bounds__(256) void k7_final(
    const float* __restrict__ x,
    const float* __restrict__ tw, const float* __restrict__ tb,
    const float* __restrict__ rw, const float* __restrict__ rb,
    const float* __restrict__ lg, const float* __restrict__ lb,
    float* __restrict__ out)
{
    extern __shared__ float s7[];
    float* Ws = s7 + S7_WS;
    float* xg = s7 + S7_XG;
    float* xr = s7 + S7_XR;
    float* yb = s7 + S7_YB;
    float* mu = s7 + S7_MU;
    float* ri = s7 + S7_RI;

    int b = blockIdx.z, t = blockIdx.y, n0 = blockIdx.x << 5;
    int tid = threadIdx.x;

    for (int idx = tid; idx < FO*192; idx += 256) { int o = idx / 192, r = idx - o*192; Ws[r*68 + o] = tw[idx]; }
    for (int idx = tid; idx < FO*FI; idx += 256) { int o = idx >> 5, f = idx & 31; Ws[(192+f)*68 + o] = rw[idx]; }
#pragma unroll
    for (int dt = 0; dt < 3; dt++) {
        int ts = t + dt - 1;
        if (ts >= 0 && ts < T) {
            const float* src = g_xgc + (((size_t)b*T + ts)*NN + n0) * FO;
            for (int idx = tid; idx < 32*FO; idx += 256) xg[dt*2048 + idx] = src[idx];
        } else {
            for (int idx = tid; idx < 32*FO; idx += 256) xg[dt*2048 + idx] = 0.f;
        }
    }
    {
        const float* src = x + (((size_t)b*T + t)*NN + n0) * FI;
        for (int idx = tid; idx < 32*FI; idx += 256) xr[idx] = src[idx];
    }
    __syncthreads();

    int og = tid & 15, nlg = tid >> 4;
    int o0 = og << 2, nl0 = nlg << 1;
    float4 tb4 = *(const float4*)(tb + o0);
    float4 rb4 = *(const float4*)(rb + o0);
    float acc0[4], acc1[4];
#pragma unroll
    for (int c = 0; c < 4; c++) {
        float bia = ((const float*)&tb4)[c] + ((const float*)&rb4)[c];
        acc0[c] = bia; acc1[c] = bia;
    }

    for (int c = 0; c < FO; c++) {
#pragma unroll
        for (int dt = 0; dt < 3; dt++) {
            float4 w = *(const float4*)(Ws + (c*3 + dt)*68 + o0);
            float xa = xg[dt*2048 + nl0*FO + c];
            float xb2 = xg[dt*2048 + nl0*FO + FO + c];
            acc0[0] += xa*w.x;  acc0[1] += xa*w.y;  acc0[2] += xa*w.z;  acc0[3] += xa*w.w;
            acc1[0] += xb2*w.x; acc1[1] += xb2*w.y; acc1[2] += xb2*w.z; acc1[3] += xb2*w.w;
        }
    }
#pragma unroll
    for (int f = 0; f < FI; f++) {
        float4 w = *(const float4*)(Ws + (192 + f)*68 + o0);
        float xa = xr[nl0*FI + f];
        float xb2 = xr[nl0*FI + FI + f];
        acc0[0] += xa*w.x;  acc0[1] += xa*w.y;  acc0[2] += xa*w.z;  acc0[3] += xa*w.w;
        acc1[0] += xb2*w.x; acc1[1] += xb2*w.y; acc1[2] += xb2*w.z; acc1[3] += xb2*w.w;
    }
#pragma unroll
    for (int c = 0; c < 4; c++) {
        float v0 = acc0[c] > 0.f ? acc0[c] : 0.f;
        float v1 = acc1[c] > 0.f ? acc1[c] : 0.f;
        yb[nl0*65 + o0 + c] = v0;
        yb[(nl0+1)*65 + o0 + c] = v1;
    }
    __syncthreads();
    if (tid < 32) {
        float m = 0.f;
#pragma unroll
        for (int o = 0; o < FO; o++) m += yb[tid*65 + o];
        m *= (1.f/FO);
        float v = 0.f;
#pragma unroll
        for (int o = 0; o < FO; o++) { float d = yb[tid*65 + o] - m; v += d*d; }
        v *= (1.f/FO);
        mu[tid] = m;
        ri[tid] = rsqrtf(v + 1e-5f);
    }
    __syncthreads();
    float4 g4 = *(const float4*)(lg + o0);
    float4 b4 = *(const float4*)(lb + o0);
#pragma unroll
    for (int j = 0; j < 2; j++) {
        int nl = nl0 + j;
        float m = mu[nl], r = ri[nl];
        float4 ov;
        ov.x = (yb[nl*65 + o0 + 0] - m)*r*g4.x + b4.x;
        ov.y = (yb[nl*65 + o0 + 1] - m)*r*g4.y + b4.y;
        ov.z = (yb[nl*65 + o0 + 2] - m)*r*g4.z + b4.z;
        ov.w = (yb[nl*65 + o0 + 3] - m)*r*g4.w + b4.w;
        *(float4*)(out + ((((size_t)b*T + t)*NN + n0 + nl) << 6) + o0) = ov;
    }
}

// ---------------- launch ----------------
extern "C" void kernel_launch(void* const* d_in, const int* in_sizes, int n_in,
                              void* d_out, int out_size)
{
    const float* x     = (const float*)d_in[0];
    const float* cheb  = (const float*)d_in[1];
    const float* wq_t  = (const float*)d_in[2];
    const float* wk_t  = (const float*)d_in[3];
    const float* wq_s  = (const float*)d_in[4];
    const float* wk_s  = (const float*)d_in[5];
    const float* theta = (const float*)d_in[6];
    const float* tw    = (const float*)d_in[7];
    const float* tbv   = (const float*)d_in[8];
    const float* rw    = (const float*)d_in[9];
    const float* rbv   = (const float*)d_in[10];
    const float* lg    = (const float*)d_in[11];
    const float* lb    = (const float*)d_in[12];
    float* out = (float*)d_out;

    cudaFuncSetAttribute(k7_final, cudaFuncAttributeMaxDynamicSharedMemorySize,
                         S7_TOTF * (int)sizeof(float));

    k1_qk<<<(B*T*NN)/256, 256>>>(x, wq_t, wk_t);
    k2_ta<<<B*T, 256>>>();
    k3_xta<<<dim3(NN/32, B), 1024>>>(x);
    k4_qk<<<(B*T*NN)/256, 256>>>(wq_s, wk_s);
    k5_sa<<<B*NN, 256>>>();
    k6_cheb_gemm<<<dim3((T*FI)/BN6, NN/BM6, B), 256>>>(cheb, theta);
    k7_final<<<dim3(NN/32, T, B), 256, S7_TOTF * (int)sizeof(float)>>>(
        x, tw, tbv, rw, rbv, lg, lb, out);
}

// round 6
// speedup vs baseline: 1.5253x; 1.4641x over previous
#include <cuda_runtime.h>
#include <math.h>
#include <stdint.h>

#define B   16
#define T   12
#define NN  2048
#define FI  32
#define FO  64
#define KC  3

// ---------------- static scratch (no allocations allowed) ----------------
__device__ float g_qt[(size_t)B*T*NN];
__device__ float g_kt[(size_t)B*T*NN];
__device__ float g_ta[(size_t)B*T*T];
__device__ __align__(16) float g_xta[(size_t)B*T*NN*FI];
__device__ __align__(16) float g_qs[(size_t)B*NN*T];   // (B,N,T) transposed
__device__ __align__(16) float g_ks[(size_t)B*NN*T];   // (B,N,T) transposed
__device__ __align__(16) float g_sa[(size_t)B*NN*NN];
__device__ __align__(16) float g_xgc[(size_t)B*T*NN*FO];

// pack {hi_half=bf16(h), lo_half=bf16(l)}
__device__ __forceinline__ unsigned bf2(float h, float l) {
    unsigned r;
    asm("cvt.rn.bf16x2.f32 %0, %1, %2;" : "=r"(r) : "f"(h), "f"(l));
    return r;
}
// m16n8k16 bf16 MMA, fp32 accumulate (sm_80+ baseline — no arch-specific target needed)
__device__ __forceinline__ void mma_bf16(float* c, const unsigned* a, const unsigned* b) {
    asm volatile(
        "mma.sync.aligned.m16n8k16.row.col.f32.bf16.bf16.f32 "
        "{%0,%1,%2,%3}, {%4,%5,%6,%7}, {%8,%9}, {%0,%1,%2,%3};"
        : "+f"(c[0]), "+f"(c[1]), "+f"(c[2]), "+f"(c[3])
        : "r"(a[0]), "r"(a[1]), "r"(a[2]), "r"(a[3]), "r"(b[0]), "r"(b[1]));
}
#define SWZ(o) ((o) ^ (((o) >> 3) & 0x70))

// ---------------- K1: qt/kt = x @ wq_t / wk_t ----------------
__global__ void k1_qk(const float* __restrict__ x,
                      const float* __restrict__ wq, const float* __restrict__ wk)
{
    __shared__ float sw[64];
    int tid = threadIdx.x;
    if (tid < 64) sw[tid] = (tid < 32) ? wq[tid] : wk[tid - 32];
    __syncthreads();
    size_t g = (size_t)blockIdx.x * 256 + tid;
    const float4* xr = (const float4*)(x + g * FI);
    float aq = 0.f, ak = 0.f;
#pragma unroll
    for (int u = 0; u < 8; u++) {
        float4 v = xr[u];
        aq += v.x*sw[u*4+0] + v.y*sw[u*4+1] + v.z*sw[u*4+2] + v.w*sw[u*4+3];
        ak += v.x*sw[32+u*4+0] + v.y*sw[32+u*4+1] + v.z*sw[32+u*4+2] + v.w*sw[32+u*4+3];
    }
    g_qt[g] = aq; g_kt[g] = ak;
}

// ---------------- K2: temporal attention ----------------
__global__ void k2_ta()
{
    int b = blockIdx.x / T, t = blockIdx.x % T;
    int tid = threadIdx.x;
    const float* q  = g_qt + ((size_t)b*T + t) * NN;
    const float* kb = g_kt + (size_t)b*T*NN;
    float p[T];
#pragma unroll
    for (int s = 0; s < T; s++) p[s] = 0.f;
    for (int n = tid; n < NN; n += 256) {
        float qv = q[n];
#pragma unroll
        for (int s = 0; s < T; s++) p[s] += qv * kb[(size_t)s*NN + n];
    }
    __shared__ float sc[T];
    if (tid < T) sc[tid] = 0.f;
    __syncthreads();
#pragma unroll
    for (int s = 0; s < T; s++) {
        float v = p[s];
        for (int off = 16; off; off >>= 1) v += __shfl_down_sync(0xffffffffu, v, off);
        if ((tid & 31) == 0) atomicAdd(&sc[s], v);
    }
    __syncthreads();
    if (tid == 0) {
        const float isN = 0.022097086912079612f;
        float sv[T], mx = -1e30f;
#pragma unroll
        for (int s = 0; s < T; s++) { sv[s] = sc[s]*isN; mx = fmaxf(mx, sv[s]); }
        float sum = 0.f;
#pragma unroll
        for (int s = 0; s < T; s++) { sv[s] = __expf(sv[s]-mx); sum += sv[s]; }
        float inv = 1.f / sum;
        float* out = g_ta + ((size_t)b*T + t) * T;
#pragma unroll
        for (int s = 0; s < T; s++) out[s] = sv[s]*inv;
    }
}

// ---------------- K3: x_ta ----------------
__global__ __launch_bounds__(1024) void k3_xta(const float* __restrict__ x)
{
    __shared__ float tas[T*T];
    int b = blockIdx.y, n0 = blockIdx.x << 5;
    int tid = threadIdx.x;
    if (tid < T*T) tas[tid] = g_ta[(size_t)b*T*T + tid];
    __syncthreads();
    int f = tid & 31, nl = tid >> 5;
    size_t base = ((size_t)b*T*NN + (n0 + nl)) * FI + f;
    float v[T];
#pragma unroll
    for (int s = 0; s < T; s++) v[s] = x[base + (size_t)s*NN*FI];
#pragma unroll
    for (int t = 0; t < T; t++) {
        float a = 0.f;
#pragma unroll
        for (int s = 0; s < T; s++) a += tas[t*T + s] * v[s];
        g_xta[base + (size_t)t*NN*FI] = a;
    }
}

// ---------------- K4: qs/ks ----------------
__global__ void k4_qk(const float* __restrict__ wq, const float* __restrict__ wk)
{
    __shared__ float sw[64];
    int tid = threadIdx.x;
    if (tid < 64) sw[tid] = (tid < 32) ? wq[tid] : wk[tid - 32];
    __syncthreads();
    size_t g = (size_t)blockIdx.x * 256 + tid;
    const float4* xr = (const float4*)(g_xta + g * FI);
    float aq = 0.f, ak = 0.f;
#pragma unroll
    for (int u = 0; u < 8; u++) {
        float4 v = xr[u];
        aq += v.x*sw[u*4+0] + v.y*sw[u*4+1] + v.z*sw[u*4+2] + v.w*sw[u*4+3];
        ak += v.x*sw[32+u*4+0] + v.y*sw[32+u*4+1] + v.z*sw[32+u*4+2] + v.w*sw[32+u*4+3];
    }
    int n = (int)(g % NN);
    size_t bt = g / NN;
    int t = (int)(bt % T);
    int b = (int)(bt / T);
    size_t o = ((size_t)b*NN + n) * T + t;
    g_qs[o] = aq; g_ks[o] = ak;
}

// ---------------- K5: spatial attention ----------------
__global__ __launch_bounds__(256) void k5_sa()
{
    __shared__ float buf[NN];
    __shared__ float red[256];
    __shared__ float qr[T];
    int b = blockIdx.x >> 11;
    int i = blockIdx.x & (NN - 1);
    int tid = threadIdx.x;
    const float* qsb = g_qs + ((size_t)b*NN + i) * T;
    const float* ksb = g_ks + (size_t)b*NN*T;
    if (tid < T) qr[tid] = qsb[tid];
    __syncthreads();
    const float isT = 0.28867513459481287f;
    float lmax = -1e30f;
    for (int m = tid; m < NN; m += 256) {
        const float4* kr = (const float4*)(ksb + (size_t)m * T);
        float4 A = kr[0], Bv = kr[1], C = kr[2];
        float s = qr[0]*A.x + qr[1]*A.y + qr[2]*A.z + qr[3]*A.w
                + qr[4]*Bv.x + qr[5]*Bv.y + qr[6]*Bv.z + qr[7]*Bv.w
                + qr[8]*C.x + qr[9]*C.y + qr[10]*C.z + qr[11]*C.w;
        s *= isT;
        buf[m] = s;
        lmax = fmaxf(lmax, s);
    }
    red[tid] = lmax; __syncthreads();
    for (int s = 128; s > 0; s >>= 1) { if (tid < s) red[tid] = fmaxf(red[tid], red[tid+s]); __syncthreads(); }
    float mx = red[0]; __syncthreads();
    float lsum = 0.f;
    for (int m = tid; m < NN; m += 256) { float e = __expf(buf[m]-mx); buf[m] = e; lsum += e; }
    red[tid] = lsum; __syncthreads();
    for (int s = 128; s > 0; s >>= 1) { if (tid < s) red[tid] += red[tid+s]; __syncthreads(); }
    float inv = 1.f / red[0];
    float* out = g_sa + ((size_t)b*NN + i) * NN;
    for (int m = tid; m < NN; m += 256) out[m] = buf[m] * inv;
}

// ---------------- K6: warp-MMA bf16-split Chebyshev GEMM + theta epilogue ----------------
// Per block (b, i0, t0): D_k[128 i][64 n] = sum_j (cheb_k*sa)[i][j] * x_ta[t(n)][j][f(n)]
// via mma.sync m16n8k16 bf16, split D = Ah@Bh + Ah@Bl + Al@Bh (fp32 acc, err ~2^-18).
// Epilogue: xgc = relu( sum_k sum_f D_k[i][tt*32+f] * theta[k][f][o] )
#define K6_BK     64
#define K6_ITERS  (NN / K6_BK)     // 32
// smem byte offsets (tiles SW128-swizzled, bf16, 128B rows)
#define OFF_AH(k)  ((k)*32768)
#define OFF_AL(k)  ((k)*32768 + 16384)
#define OFF_BH     98304
#define OFF_BL     106496
// epilogue overlay (floats)
#define CS_STR     68
#define CS_K       (128*CS_STR)            // 8704 floats per k
#define THS_OFF    (3*CS_K)                // 26112 floats
#define K6_SMEM    ((THS_OFF + KC*FI*FO) * 4)   // 129024 bytes

__global__ __launch_bounds__(256, 1)
void k6_mma(const float* __restrict__ cheb, const float* __restrict__ theta)
{
    extern __shared__ __align__(1024) char smem[];
    const int b  = blockIdx.z;
    const int i0 = blockIdx.y * 128;
    const int t0 = blockIdx.x * 2;
    const int tid = threadIdx.x, wid = tid >> 5, lane = tid & 31;
    const int g = lane >> 2, q = lane & 3;
    const int wm = wid >> 1, wn = wid & 1;

    const float* sab = g_sa  + (size_t)b * NN * NN;
    const float* xb  = g_xta + (size_t)b * T * NN * FI;

    float acc[3][2][4][4];
#pragma unroll
    for (int k = 0; k < 3; k++)
#pragma unroll
        for (int mt = 0; mt < 2; mt++)
#pragma unroll
            for (int nt = 0; nt < 4; nt++)
#pragma unroll
                for (int c = 0; c < 4; c++) acc[k][mt][nt][c] = 0.f;

    for (int iter = 0; iter < K6_ITERS; iter++) {
        const int j0 = iter * K6_BK;
        if (iter > 0) __syncthreads();    // prev compute done before overwrite

        // ---- produce A tiles: rows of (cheb_k * sa), bf16 hi/lo, SW128 K-major ----
#pragma unroll
        for (int p = 0; p < 4; p++) {
            int ii = p*32 + wid*4 + (lane >> 3);     // 0..127
            int jq = lane & 7;                        // 8-elem chunk
            size_t go = (size_t)(i0 + ii) * NN + j0 + jq*8;
            float4 s0 = *(const float4*)(sab + go);
            float4 s1 = *(const float4*)(sab + go + 4);
            uint32_t sw = SWZ((uint32_t)(ii*128 + jq*16));
#pragma unroll
            for (int k = 0; k < 3; k++) {
                const float* cb = cheb + (size_t)k*NN*NN + go;
                float4 c0 = *(const float4*)(cb);
                float4 c1 = *(const float4*)(cb + 4);
                float a0 = c0.x*s0.x, a1 = c0.y*s0.y, a2 = c0.z*s0.z, a3 = c0.w*s0.w;
                float a4 = c1.x*s1.x, a5 = c1.y*s1.y, a6 = c1.z*s1.z, a7 = c1.w*s1.w;
                uint4 hv;
                hv.x = bf2(a1, a0); hv.y = bf2(a3, a2); hv.z = bf2(a5, a4); hv.w = bf2(a7, a6);
                float h0 = __uint_as_float(hv.x << 16), h1 = __uint_as_float(hv.x & 0xFFFF0000u);
                float h2 = __uint_as_float(hv.y << 16), h3 = __uint_as_float(hv.y & 0xFFFF0000u);
                float h4 = __uint_as_float(hv.z << 16), h5 = __uint_as_float(hv.z & 0xFFFF0000u);
                float h6 = __uint_as_float(hv.w << 16), h7 = __uint_as_float(hv.w & 0xFFFF0000u);
                uint4 lv;
                lv.x = bf2(a1 - h1, a0 - h0); lv.y = bf2(a3 - h3, a2 - h2);
                lv.z = bf2(a5 - h5, a4 - h4); lv.w = bf2(a7 - h7, a6 - h6);
                *(uint4*)(smem + OFF_AH(k) + sw) = hv;
                *(uint4*)(smem + OFF_AL(k) + sw) = lv;
            }
        }
        // ---- produce B tiles: B[n][j] = x_ta[t0 + n/32][j][n%32], hi/lo ----
#pragma unroll
        for (int pass = 0; pass < 8; pass++) {
            int n = pass*8 + wid;                   // 0..63
            int t = t0 + (n >> 5), f = n & 31;
            const float* src = xb + ((size_t)t*NN + (j0 + 2*lane)) * FI + f;
            float x0 = src[0], x1 = src[FI];
            unsigned hi2 = bf2(x1, x0);
            float h0 = __uint_as_float(hi2 << 16), h1 = __uint_as_float(hi2 & 0xFFFF0000u);
            unsigned lo2 = bf2(x1 - h1, x0 - h0);
            uint32_t sw = SWZ((uint32_t)(n*128 + lane*4));
            *(unsigned*)(smem + OFF_BH + sw) = hi2;
            *(unsigned*)(smem + OFF_BL + sw) = lo2;
        }
        __syncthreads();

        // ---- compute: mma over 4 K=16 steps ----
#pragma unroll
        for (int kk = 0; kk < 4; kk++) {
            const int kb = kk*32 + q*4;            // byte offset in 128B row
            unsigned bh[4][2], bl[4][2];
#pragma unroll
            for (int nt = 0; nt < 4; nt++) {
                uint32_t r = (uint32_t)((wn*32 + nt*8 + g)*128 + kb);
                uint32_t o0 = SWZ(r), o1 = SWZ(r + 16);
                bh[nt][0] = *(const unsigned*)(smem + OFF_BH + o0);
                bh[nt][1] = *(const unsigned*)(smem + OFF_BH + o1);
                bl[nt][0] = *(const unsigned*)(smem + OFF_BL + o0);
                bl[nt][1] = *(const unsigned*)(smem + OFF_BL + o1);
            }
#pragma unroll
            for (int k = 0; k < 3; k++) {
                unsigned af[2][4];
#pragma unroll
                for (int mt = 0; mt < 2; mt++) {
                    uint32_t r0 = (uint32_t)((wm*32 + mt*16 + g)*128 + kb);
                    uint32_t r1 = (uint32_t)((wm*32 + mt*16 + 8 + g)*128 + kb);
                    af[mt][0] = *(const unsigned*)(smem + OFF_AH(k) + SWZ(r0));
                    af[mt][1] = *(const unsigned*)(smem + OFF_AH(k) + SWZ(r1));
                    af[mt][2] = *(const unsigned*)(smem + OFF_AH(k) + SWZ(r0 + 16));
                    af[mt][3] = *(const unsigned*)(smem + OFF_AH(k) + SWZ(r1 + 16));
                }
#pragma unroll
                for (int mt = 0; mt < 2; mt++)
#pragma unroll
                    for (int nt = 0; nt < 4; nt++) {
                        mma_bf16(acc[k][mt][nt], af[mt], bh[nt]);
                        mma_bf16(acc[k][mt][nt], af[mt], bl[nt]);
                    }
#pragma unroll
                for (int mt = 0; mt < 2; mt++) {
                    uint32_t r0 = (uint32_t)((wm*32 + mt*16 + g)*128 + kb);
                    uint32_t r1 = (uint32_t)((wm*32 + mt*16 + 8 + g)*128 + kb);
                    af[mt][0] = *(const unsigned*)(smem + OFF_AL(k) + SWZ(r0));
                    af[mt][1] = *(const unsigned*)(smem + OFF_AL(k) + SWZ(r1));
                    af[mt][2] = *(const unsigned*)(smem + OFF_AL(k) + SWZ(r0 + 16));
                    af[mt][3] = *(const unsigned*)(smem + OFF_AL(k) + SWZ(r1 + 16));
                }
#pragma unroll
                for (int mt = 0; mt < 2; mt++)
#pragma unroll
                    for (int nt = 0; nt < 4; nt++)
                        mma_bf16(acc[k][mt][nt], af[mt], bh[nt]);
            }
        }
    }
    __syncthreads();

    // ---- stage accumulators to smem (overlay A region) ----
    float* Cs = (float*)smem;
#pragma unroll
    for (int k = 0; k < 3; k++)
#pragma unroll
        for (int mt = 0; mt < 2; mt++)
#pragma unroll
            for (int nt = 0; nt < 4; nt++) {
                int row = wm*32 + mt*16 + g;
                int col = wn*32 + nt*8 + q*2;
                float2 v0 = make_float2(acc[k][mt][nt][0], acc[k][mt][nt][1]);
                float2 v1 = make_float2(acc[k][mt][nt][2], acc[k][mt][nt][3]);
                *(float2*)(Cs + k*CS_K + row*CS_STR + col) = v0;
                *(float2*)(Cs + k*CS_K + (row + 8)*CS_STR + col) = v1;
            }
    // theta into smem (overlay B region)
    float* ths = Cs + THS_OFF;                 // [3][32][64]
    for (int idx = tid; idx < KC*FI*FO; idx += 256) ths[idx] = theta[idx];
    __syncthreads();

    // ---- epilogue: out[i][tt][o] = relu( sum_k sum_f D_k[i][tt*32+f]*th[k][f][o] ) ----
    {
        const int i = tid >> 1, half = tid & 1;
        float out0[32], out1[32];
#pragma unroll
        for (int o = 0; o < 32; o++) { out0[o] = 0.f; out1[o] = 0.f; }
#pragma unroll
        for (int k = 0; k < 3; k++) {
            const float* cr = Cs + k*CS_K + i*CS_STR;
#pragma unroll
            for (int f4 = 0; f4 < 8; f4++) {
                float4 c0 = *(const float4*)(cr + f4*4);
                float4 c1 = *(const float4*)(cr + 32 + f4*4);
                const float* cf0 = (const float*)&c0;
                const float* cf1 = (const float*)&c1;
#pragma unroll
                for (int j = 0; j < 4; j++) {
                    float v0 = cf0[j], v1 = cf1[j];
                    const float* th = ths + (k*32 + f4*4 + j)*64 + half*32;
#pragma unroll
                    for (int oq = 0; oq < 8; oq++) {
                        float4 t4 = *(const float4*)(th + oq*4);
                        out0[oq*4+0] += v0*t4.x; out0[oq*4+1] += v0*t4.y;
                        out0[oq*4+2] += v0*t4.z; out0[oq*4+3] += v0*t4.w;
                        out1[oq*4+0] += v1*t4.x; out1[oq*4+1] += v1*t4.y;
                        out1[oq*4+2] += v1*t4.z; out1[oq*4+3] += v1*t4.w;
                    }
                }
            }
        }
        size_t base0 = (((size_t)b*T + t0    )*NN + i0 + i)*FO + half*32;
        size_t base1 = (((size_t)b*T + t0 + 1)*NN + i0 + i)*FO + half*32;
#pragma unroll
        for (int oq = 0; oq < 8; oq++) {
            float4 v0, v1;
            v0.x = fmaxf(out0[oq*4+0], 0.f); v0.y = fmaxf(out0[oq*4+1], 0.f);
            v0.z = fmaxf(out0[oq*4+2], 0.f); v0.w = fmaxf(out0[oq*4+3], 0.f);
            v1.x = fmaxf(out1[oq*4+0], 0.f); v1.y = fmaxf(out1[oq*4+1], 0.f);
            v1.z = fmaxf(out1[oq*4+2], 0.f); v1.w = fmaxf(out1[oq*4+3], 0.f);
            *(float4*)(g_xgc + base0 + oq*4) = v0;
            *(float4*)(g_xgc + base1 + oq*4) = v1;
        }
    }
}

// ---------------- K7: temporal conv + residual conv + relu + layernorm ----------------
#define S7_WS   0
#define S7_XG   15232
#define S7_XR   (S7_XG + 6144)
#define S7_YB   (S7_XR + 1024)
#define S7_MU   (S7_YB + 2080)
#define S7_RI   (S7_MU + 32)
#define S7_TOTF (S7_RI + 32)

__global__ __launch_bounds__(256) void k7_final(
    const float* __restrict__ x,
    const float* __restrict__ tw, const float* __restrict__ tb,
    const float* __restrict__ rw, const float* __restrict__ rb,
    const float* __restrict__ lg, const float* __restrict__ lb,
    float* __restrict__ out)
{
    extern __shared__ float s7[];
    float* Ws = s7 + S7_WS;
    float* xg = s7 + S7_XG;
    float* xr = s7 + S7_XR;
    float* yb = s7 + S7_YB;
    float* mu = s7 + S7_MU;
    float* ri = s7 + S7_RI;

    int b = blockIdx.z, t = blockIdx.y, n0 = blockIdx.x << 5;
    int tid = threadIdx.x;

    for (int idx = tid; idx < FO*192; idx += 256) { int o = idx / 192, r = idx - o*192; Ws[r*68 + o] = tw[idx]; }
    for (int idx = tid; idx < FO*FI; idx += 256) { int o = idx >> 5, f = idx & 31; Ws[(192+f)*68 + o] = rw[idx]; }
#pragma unroll
    for (int dt = 0; dt < 3; dt++) {
        int ts = t + dt - 1;
        if (ts >= 0 && ts < T) {
            const float* src = g_xgc + (((size_t)b*T + ts)*NN + n0) * FO;
            for (int idx = tid; idx < 32*FO; idx += 256) xg[dt*2048 + idx] = src[idx];
        } else {
            for (int idx = tid; idx < 32*FO; idx += 256) xg[dt*2048 + idx] = 0.f;
        }
    }
    {
        const float* src = x + (((size_t)b*T + t)*NN + n0) * FI;
        for (int idx = tid; idx < 32*FI; idx += 256) xr[idx] = src[idx];
    }
    __syncthreads();

    int og = tid & 15, nlg = tid >> 4;
    int o0 = og << 2, nl0 = nlg << 1;
    float4 tb4 = *(const float4*)(tb + o0);
    float4 rb4 = *(const float4*)(rb + o0);
    float acc0[4], acc1[4];
#pragma unroll
    for (int c = 0; c < 4; c++) {
        float bia = ((const float*)&tb4)[c] + ((const float*)&rb4)[c];
        acc0[c] = bia; acc1[c] = bia;
    }

    for (int c = 0; c < FO; c++) {
#pragma unroll
        for (int dt = 0; dt < 3; dt++) {
            float4 w = *(const float4*)(Ws + (c*3 + dt)*68 + o0);
            float xa = xg[dt*2048 + nl0*FO + c];
            float xb2 = xg[dt*2048 + nl0*FO + FO + c];
            acc0[0] += xa*w.x;  acc0[1] += xa*w.y;  acc0[2] += xa*w.z;  acc0[3] += xa*w.w;
            acc1[0] += xb2*w.x; acc1[1] += xb2*w.y; acc1[2] += xb2*w.z; acc1[3] += xb2*w.w;
        }
    }
#pragma unroll
    for (int f = 0; f < FI; f++) {
        float4 w = *(const float4*)(Ws + (192 + f)*68 + o0);
        float xa = xr[nl0*FI + f];
        float xb2 = xr[nl0*FI + FI + f];
        acc0[0] += xa*w.x;  acc0[1] += xa*w.y;  acc0[2] += xa*w.z;  acc0[3] += xa*w.w;
        acc1[0] += xb2*w.x; acc1[1] += xb2*w.y; acc1[2] += xb2*w.z; acc1[3] += xb2*w.w;
    }
#pragma unroll
    for (int c = 0; c < 4; c++) {
        float v0 = acc0[c] > 0.f ? acc0[c] : 0.f;
        float v1 = acc1[c] > 0.f ? acc1[c] : 0.f;
        yb[nl0*65 + o0 + c] = v0;
        yb[(nl0+1)*65 + o0 + c] = v1;
    }
    __syncthreads();
    if (tid < 32) {
        float m = 0.f;
#pragma unroll
        for (int o = 0; o < FO; o++) m += yb[tid*65 + o];
        m *= (1.f/FO);
        float v = 0.f;
#pragma unroll
        for (int o = 0; o < FO; o++) { float d = yb[tid*65 + o] - m; v += d*d; }
        v *= (1.f/FO);
        mu[tid] = m;
        ri[tid] = rsqrtf(v + 1e-5f);
    }
    __syncthreads();
    float4 g4 = *(const float4*)(lg + o0);
    float4 b4 = *(const float4*)(lb + o0);
#pragma unroll
    for (int j = 0; j < 2; j++) {
        int nl = nl0 + j;
        float m = mu[nl], r = ri[nl];
        float4 ov;
        ov.x = (yb[nl*65 + o0 + 0] - m)*r*g4.x + b4.x;
        ov.y = (yb[nl*65 + o0 + 1] - m)*r*g4.y + b4.y;
        ov.z = (yb[nl*65 + o0 + 2] - m)*r*g4.z + b4.z;
        ov.w = (yb[nl*65 + o0 + 3] - m)*r*g4.w + b4.w;
        *(float4*)(out + ((((size_t)b*T + t)*NN + n0 + nl) << 6) + o0) = ov;
    }
}

// ---------------- launch ----------------
extern "C" void kernel_launch(void* const* d_in, const int* in_sizes, int n_in,
                              void* d_out, int out_size)
{
    const float* x     = (const float*)d_in[0];
    const float* cheb  = (const float*)d_in[1];
    const float* wq_t  = (const float*)d_in[2];
    const float* wk_t  = (const float*)d_in[3];
    const float* wq_s  = (const float*)d_in[4];
    const float* wk_s  = (const float*)d_in[5];
    const float* theta = (const float*)d_in[6];
    const float* tw    = (const float*)d_in[7];
    const float* tbv   = (const float*)d_in[8];
    const float* rw    = (const float*)d_in[9];
    const float* rbv   = (const float*)d_in[10];
    const float* lg    = (const float*)d_in[11];
    const float* lb    = (const float*)d_in[12];
    float* out = (float*)d_out;

    cudaFuncSetAttribute(k6_mma, cudaFuncAttributeMaxDynamicSharedMemorySize, K6_SMEM);
    cudaFuncSetAttribute(k7_final, cudaFuncAttributeMaxDynamicSharedMemorySize,
                         S7_TOTF * (int)sizeof(float));

    k1_qk<<<(B*T*NN)/256, 256>>>(x, wq_t, wk_t);
    k2_ta<<<B*T, 256>>>();
    k3_xta<<<dim3(NN/32, B), 1024>>>(x);
    k4_qk<<<(B*T*NN)/256, 256>>>(wq_s, wk_s);
    k5_sa<<<B*NN, 256>>>();
    k6_mma<<<dim3(T/2, NN/128, B), 256, K6_SMEM>>>(cheb, theta);
    k7_final<<<dim3(NN/32, T, B), 256, S7_TOTF * (int)sizeof(float)>>>(
        x, tw, tbv, rw, rbv, lg, lb, out);
}

// round 9
// speedup vs baseline: 1.5898x; 1.0423x over previous
#include <cuda_runtime.h>
#include <math.h>
#include <stdint.h>

#define B   16
#define T   12
#define NN  2048
#define FI  32
#define FO  64
#define KC  3

// ---------------- static scratch (no allocations allowed) ----------------
__device__ float g_qt[(size_t)B*T*NN];
__device__ float g_kt[(size_t)B*T*NN];
__device__ float g_ta[(size_t)B*T*T];
__device__ __align__(16) float g_xta[(size_t)B*T*NN*FI];
__device__ __align__(16) float g_qs[(size_t)B*NN*T];   // (B,N,T) transposed
__device__ __align__(16) float g_ks[(size_t)B*NN*T];   // (B,N,T) transposed
__device__ __align__(16) float g_sa[(size_t)B*NN*NN];
__device__ __align__(16) float g_xgc[(size_t)B*T*NN*FO];

// pack {hi_half=bf16(h), lo_half=bf16(l)}
__device__ __forceinline__ unsigned bf2(float h, float l) {
    unsigned r;
    asm("cvt.rn.bf16x2.f32 %0, %1, %2;" : "=r"(r) : "f"(h), "f"(l));
    return r;
}
// m16n8k16 bf16 MMA, fp32 accumulate (sm_80+ baseline PTX)
__device__ __forceinline__ void mma_bf16(float* c, const unsigned* a, const unsigned* b) {
    asm volatile(
        "mma.sync.aligned.m16n8k16.row.col.f32.bf16.bf16.f32 "
        "{%0,%1,%2,%3}, {%4,%5,%6,%7}, {%8,%9}, {%0,%1,%2,%3};"
        : "+f"(c[0]), "+f"(c[1]), "+f"(c[2]), "+f"(c[3])
        : "r"(a[0]), "r"(a[1]), "r"(a[2]), "r"(a[3]), "r"(b[0]), "r"(b[1]));
}
__device__ __forceinline__ void ldsm4(unsigned& r0, unsigned& r1, unsigned& r2, unsigned& r3,
                                      uint32_t a) {
    asm volatile("ldmatrix.sync.aligned.m8n8.x4.shared.b16 {%0,%1,%2,%3}, [%4];"
                 : "=r"(r0), "=r"(r1), "=r"(r2), "=r"(r3) : "r"(a));
}
__device__ __forceinline__ uint32_t s2u(const void* p) {
    uint32_t a;
    asm("{ .reg .u64 t; cvta.to.shared.u64 t, %1; cvt.u32.u64 %0, t; }" : "=r"(a) : "l"(p));
    return a;
}
#define SWZ(o) ((o) ^ (((o) >> 3) & 0x70))

// ---------------- K1: qt/kt = x @ wq_t / wk_t ----------------
__global__ void k1_qk(const float* __restrict__ x,
                      const float* __restrict__ wq, const float* __restrict__ wk)
{
    __shared__ float sw[64];
    int tid = threadIdx.x;
    if (tid < 64) sw[tid] = (tid < 32) ? wq[tid] : wk[tid - 32];
    __syncthreads();
    size_t g = (size_t)blockIdx.x * 256 + tid;
    const float4* xr = (const float4*)(x + g * FI);
    float aq = 0.f, ak = 0.f;
#pragma unroll
    for (int u = 0; u < 8; u++) {
        float4 v = xr[u];
        aq += v.x*sw[u*4+0] + v.y*sw[u*4+1] + v.z*sw[u*4+2] + v.w*sw[u*4+3];
        ak += v.x*sw[32+u*4+0] + v.y*sw[32+u*4+1] + v.z*sw[32+u*4+2] + v.w*sw[32+u*4+3];
    }
    g_qt[g] = aq; g_kt[g] = ak;
}

// ---------------- K2: temporal attention ----------------
__global__ void k2_ta()
{
    int b = blockIdx.x / T, t = blockIdx.x % T;
    int tid = threadIdx.x;
    const float* q  = g_qt + ((size_t)b*T + t) * NN;
    const float* kb = g_kt + (size_t)b*T*NN;
    float p[T];
#pragma unroll
    for (int s = 0; s < T; s++) p[s] = 0.f;
    for (int n = tid; n < NN; n += 256) {
        float qv = q[n];
#pragma unroll
        for (int s = 0; s < T; s++) p[s] += qv * kb[(size_t)s*NN + n];
    }
    __shared__ float sc[T];
    if (tid < T) sc[tid] = 0.f;
    __syncthreads();
#pragma unroll
    for (int s = 0; s < T; s++) {
        float v = p[s];
        for (int off = 16; off; off >>= 1) v += __shfl_down_sync(0xffffffffu, v, off);
        if ((tid & 31) == 0) atomicAdd(&sc[s], v);
    }
    __syncthreads();
    if (tid == 0) {
        const float isN = 0.022097086912079612f;
        float sv[T], mx = -1e30f;
#pragma unroll
        for (int s = 0; s < T; s++) { sv[s] = sc[s]*isN; mx = fmaxf(mx, sv[s]); }
        float sum = 0.f;
#pragma unroll
        for (int s = 0; s < T; s++) { sv[s] = __expf(sv[s]-mx); sum += sv[s]; }
        float inv = 1.f / sum;
        float* out = g_ta + ((size_t)b*T + t) * T;
#pragma unroll
        for (int s = 0; s < T; s++) out[s] = sv[s]*inv;
    }
}

// ---------------- K3: x_ta ----------------
__global__ __launch_bounds__(1024) void k3_xta(const float* __restrict__ x)
{
    __shared__ float tas[T*T];
    int b = blockIdx.y, n0 = blockIdx.x << 5;
    int tid = threadIdx.x;
    if (tid < T*T) tas[tid] = g_ta[(size_t)b*T*T + tid];
    __syncthreads();
    int f = tid & 31, nl = tid >> 5;
    size_t base = ((size_t)b*T*NN + (n0 + nl)) * FI + f;
    float v[T];
#pragma unroll
    for (int s = 0; s < T; s++) v[s] = x[base + (size_t)s*NN*FI];
#pragma unroll
    for (int t = 0; t < T; t++) {
        float a = 0.f;
#pragma unroll
        for (int s = 0; s < T; s++) a += tas[t*T + s] * v[s];
        g_xta[base + (size_t)t*NN*FI] = a;
    }
}

// ---------------- K4: qs/ks ----------------
__global__ void k4_qk(const float* __restrict__ wq, const float* __restrict__ wk)
{
    __shared__ float sw[64];
    int tid = threadIdx.x;
    if (tid < 64) sw[tid] = (tid < 32) ? wq[tid] : wk[tid - 32];
    __syncthreads();
    size_t g = (size_t)blockIdx.x * 256 + tid;
    const float4* xr = (const float4*)(g_xta + g * FI);
    float aq = 0.f, ak = 0.f;
#pragma unroll
    for (int u = 0; u < 8; u++) {
        float4 v = xr[u];
        aq += v.x*sw[u*4+0] + v.y*sw[u*4+1] + v.z*sw[u*4+2] + v.w*sw[u*4+3];
        ak += v.x*sw[32+u*4+0] + v.y*sw[32+u*4+1] + v.z*sw[32+u*4+2] + v.w*sw[32+u*4+3];
    }
    int n = (int)(g % NN);
    size_t bt = g / NN;
    int t = (int)(bt % T);
    int b = (int)(bt / T);
    size_t o = ((size_t)b*NN + n) * T + t;
    g_qs[o] = aq; g_ks[o] = ak;
}

// ---------------- K5: spatial attention ----------------
__global__ __launch_bounds__(256) void k5_sa()
{
    __shared__ float buf[NN];
    __shared__ float red[256];
    __shared__ float qr[T];
    int b = blockIdx.x >> 11;
    int i = blockIdx.x & (NN - 1);
    int tid = threadIdx.x;
    const float* qsb = g_qs + ((size_t)b*NN + i) * T;
    const float* ksb = g_ks + (size_t)b*NN*T;
    if (tid < T) qr[tid] = qsb[tid];
    __syncthreads();
    const float isT = 0.28867513459481287f;
    float lmax = -1e30f;
    for (int m = tid; m < NN; m += 256) {
        const float4* kr = (const float4*)(ksb + (size_t)m * T);
        float4 A = kr[0], Bv = kr[1], C = kr[2];
        float s = qr[0]*A.x + qr[1]*A.y + qr[2]*A.z + qr[3]*A.w
                + qr[4]*Bv.x + qr[5]*Bv.y + qr[6]*Bv.z + qr[7]*Bv.w
                + qr[8]*C.x + qr[9]*C.y + qr[10]*C.z + qr[11]*C.w;
        s *= isT;
        buf[m] = s;
        lmax = fmaxf(lmax, s);
    }
    red[tid] = lmax; __syncthreads();
    for (int s = 128; s > 0; s >>= 1) { if (tid < s) red[tid] = fmaxf(red[tid], red[tid+s]); __syncthreads(); }
    float mx = red[0]; __syncthreads();
    float lsum = 0.f;
    for (int m = tid; m < NN; m += 256) { float e = __expf(buf[m]-mx); buf[m] = e; lsum += e; }
    red[tid] = lsum; __syncthreads();
    for (int s = 128; s > 0; s >>= 1) { if (tid < s) red[tid] += red[tid+s]; __syncthreads(); }
    float inv = 1.f / red[0];
    float* out = g_sa + ((size_t)b*NN + i) * NN;
    for (int m = tid; m < NN; m += 256) out[m] = buf[m] * inv;
}

// ---------------- K6: warp-MMA bf16-split Chebyshev GEMM + theta epilogue ----------------
// 512 threads, 16 warps in 4(m) x 4(n) grid; warp tile 32m x 16n; ldmatrix fragment loads.
// D_k = Ah@Bh + Ah@Bl + Al@Bh in fp32 acc (err ~2^-18).
#define K6_BK     64
#define K6_ITERS  (NN / K6_BK)     // 32
// smem byte offsets (tiles SW128-swizzled, bf16, 128B rows)
#define OFF_AH(k)  ((k)*32768)
#define OFF_AL(k)  ((k)*32768 + 16384)
#define OFF_BH     98304
#define OFF_BL     106496
// epilogue overlay (floats)
#define CS_STR     68
#define CS_K       (128*CS_STR)            // 8704 floats per k
#define THS_OFF    (3*CS_K)                // 26112 floats
#define K6_SMEM    ((THS_OFF + KC*FI*FO) * 4)   // 129024 bytes

__global__ __launch_bounds__(512, 1)
void k6_mma(const float* __restrict__ cheb, const float* __restrict__ theta)
{
    extern __shared__ __align__(1024) char smem[];
    const int b  = blockIdx.z;
    const int i0 = blockIdx.y * 128;
    const int t0 = blockIdx.x * 2;
    const int tid = threadIdx.x, wid = tid >> 5, lane = tid & 31;
    const int g = lane >> 2, q = lane & 3;
    const int wm = wid & 3, wn = wid >> 2;
    const uint32_t sb = s2u(smem);

    const float* sab = g_sa  + (size_t)b * NN * NN;
    const float* xb  = g_xta + (size_t)b * T * NN * FI;

    // ldmatrix per-lane base byte offsets (within a tile)
    const uint32_t aRow0 = (uint32_t)((wm*32 + ((lane >> 3) & 1)*8 + (lane & 7)) * 128
                                      + (lane >> 4) * 16);
    const uint32_t aRow1 = aRow0 + 16*128;
    const uint32_t bRow  = (uint32_t)((wn*16 + ((lane >> 4) & 1)*8 + (lane & 7)) * 128
                                      + ((lane >> 3) & 1) * 16);

    float acc[3][2][2][4];
#pragma unroll
    for (int k = 0; k < 3; k++)
#pragma unroll
        for (int mt = 0; mt < 2; mt++)
#pragma unroll
            for (int nt = 0; nt < 2; nt++)
#pragma unroll
                for (int c = 0; c < 4; c++) acc[k][mt][nt][c] = 0.f;

    for (int iter = 0; iter < K6_ITERS; iter++) {
        const int j0 = iter * K6_BK;
        if (iter > 0) __syncthreads();    // prev compute done before overwrite

        // ---- produce A tiles: rows of (cheb_k * sa), bf16 hi/lo, SW128 K-major ----
#pragma unroll
        for (int p = 0; p < 2; p++) {
            int ii = p*64 + wid*4 + (lane >> 3);     // 0..127
            int jq = lane & 7;                        // 8-elem chunk
            size_t go = (size_t)(i0 + ii) * NN + j0 + jq*8;
            float4 s0 = *(const float4*)(sab + go);
            float4 s1 = *(const float4*)(sab + go + 4);
            uint32_t sw = SWZ((uint32_t)(ii*128 + jq*16));
#pragma unroll
            for (int k = 0; k < 3; k++) {
                const float* cb = cheb + (size_t)k*NN*NN + go;
                float4 c0 = *(const float4*)(cb);
                float4 c1 = *(const float4*)(cb + 4);
                float a0 = c0.x*s0.x, a1 = c0.y*s0.y, a2 = c0.z*s0.z, a3 = c0.w*s0.w;
                float a4 = c1.x*s1.x, a5 = c1.y*s1.y, a6 = c1.z*s1.z, a7 = c1.w*s1.w;
                uint4 hv;
                hv.x = bf2(a1, a0); hv.y = bf2(a3, a2); hv.z = bf2(a5, a4); hv.w = bf2(a7, a6);
                float h0 = __uint_as_float(hv.x << 16), h1 = __uint_as_float(hv.x & 0xFFFF0000u);
                float h2 = __uint_as_float(hv.y << 16), h3 = __uint_as_float(hv.y & 0xFFFF0000u);
                float h4 = __uint_as_float(hv.z << 16), h5 = __uint_as_float(hv.z & 0xFFFF0000u);
                float h6 = __uint_as_float(hv.w << 16), h7 = __uint_as_float(hv.w & 0xFFFF0000u);
                uint4 lv;
                lv.x = bf2(a1 - h1, a0 - h0); lv.y = bf2(a3 - h3, a2 - h2);
                lv.z = bf2(a5 - h5, a4 - h4); lv.w = bf2(a7 - h7, a6 - h6);
                *(uint4*)(smem + OFF_AH(k) + sw) = hv;
                *(uint4*)(smem + OFF_AL(k) + sw) = lv;
            }
        }
        // ---- produce B tiles: B[n][j] = x_ta[t0 + n/32][j][n%32], hi/lo ----
#pragma unroll
        for (int pass = 0; pass < 4; pass++) {
            int n = pass*16 + wid;                  // 0..63
            int t = t0 + (n >> 5), f = n & 31;
            const float* src = xb + ((size_t)t*NN + (j0 + 2*lane)) * FI + f;
            float x0 = src[0], x1 = src[FI];
            unsigned hi2 = bf2(x1, x0);
            float h0 = __uint_as_float(hi2 << 16), h1 = __uint_as_float(hi2 & 0xFFFF0000u);
            unsigned lo2 = bf2(x1 - h1, x0 - h0);
            uint32_t sw = SWZ((uint32_t)(n*128 + lane*4));
            *(unsigned*)(smem + OFF_BH + sw) = hi2;
            *(unsigned*)(smem + OFF_BL + sw) = lo2;
        }
        __syncthreads();

        // ---- compute: ldmatrix + mma over 4 K=16 steps ----
#pragma unroll
        for (int kk = 0; kk < 4; kk++) {
            const uint32_t kb = (uint32_t)kk * 32;
            unsigned bh[4], bl[4];
            ldsm4(bh[0], bh[1], bh[2], bh[3], sb + OFF_BH + SWZ(bRow + kb));
            ldsm4(bl[0], bl[1], bl[2], bl[3], sb + OFF_BL + SWZ(bRow + kb));
#pragma unroll
            for (int k = 0; k < 3; k++) {
                unsigned a0[4], a1[4];
                ldsm4(a0[0], a0[1], a0[2], a0[3], sb + OFF_AH(k) + SWZ(aRow0 + kb));
                ldsm4(a1[0], a1[1], a1[2], a1[3], sb + OFF_AH(k) + SWZ(aRow1 + kb));
                mma_bf16(acc[k][0][0], a0, bh + 0); mma_bf16(acc[k][0][1], a0, bh + 2);
                mma_bf16(acc[k][1][0], a1, bh + 0); mma_bf16(acc[k][1][1], a1, bh + 2);
                mma_bf16(acc[k][0][0], a0, bl + 0); mma_bf16(acc[k][0][1], a0, bl + 2);
                mma_bf16(acc[k][1][0], a1, bl + 0); mma_bf16(acc[k][1][1], a1, bl + 2);
                ldsm4(a0[0], a0[1], a0[2], a0[3], sb + OFF_AL(k) + SWZ(aRow0 + kb));
                ldsm4(a1[0], a1[1], a1[2], a1[3], sb + OFF_AL(k) + SWZ(aRow1 + kb));
                mma_bf16(acc[k][0][0], a0, bh + 0); mma_bf16(acc[k][0][1], a0, bh + 2);
                mma_bf16(acc[k][1][0], a1, bh + 0); mma_bf16(acc[k][1][1], a1, bh + 2);
            }
        }
    }
    __syncthreads();

    // ---- stage accumulators to smem (overlay A region) ----
    float* Cs = (float*)smem;
#pragma unroll
    for (int k = 0; k < 3; k++)
#pragma unroll
        for (int mt = 0; mt < 2; mt++)
#pragma unroll
            for (int nt = 0; nt < 2; nt++) {
                int row = wm*32 + mt*16 + g;
                int col = wn*16 + nt*8 + q*2;
                float2 v0 = make_float2(acc[k][mt][nt][0], acc[k][mt][nt][1]);
                float2 v1 = make_float2(acc[k][mt][nt][2], acc[k][mt][nt][3]);
                *(float2*)(Cs + k*CS_K + row*CS_STR + col) = v0;
                *(float2*)(Cs + k*CS_K + (row + 8)*CS_STR + col) = v1;
            }
    // theta into smem (overlay B region)
    float* ths = Cs + THS_OFF;                 // [3][32][64]
    for (int idx = tid; idx < KC*FI*FO; idx += 512) ths[idx] = theta[idx];
    __syncthreads();

    // ---- epilogue: out[i][tt][o] = relu( sum_k sum_f D_k[i][tt*32+f]*th[k][f][o] ) ----
    {
        const int i = tid >> 2, seg = tid & 3, o0 = seg*16;
        float out0[16], out1[16];
#pragma unroll
        for (int o = 0; o < 16; o++) { out0[o] = 0.f; out1[o] = 0.f; }
#pragma unroll
        for (int k = 0; k < 3; k++) {
            const float* cr = Cs + k*CS_K + i*CS_STR;
#pragma unroll
            for (int f4 = 0; f4 < 8; f4++) {
                float4 c0 = *(const float4*)(cr + f4*4);
                float4 c1 = *(const float4*)(cr + 32 + f4*4);
                const float* cf0 = (const float*)&c0;
                const float* cf1 = (const float*)&c1;
#pragma unroll
                for (int j = 0; j < 4; j++) {
                    float v0 = cf0[j], v1 = cf1[j];
                    const float* th = ths + (k*32 + f4*4 + j)*64 + o0;
#pragma unroll
                    for (int oq = 0; oq < 4; oq++) {
                        float4 t4 = *(const float4*)(th + oq*4);
                        out0[oq*4+0] += v0*t4.x; out0[oq*4+1] += v0*t4.y;
                        out0[oq*4+2] += v0*t4.z; out0[oq*4+3] += v0*t4.w;
                        out1[oq*4+0] += v1*t4.x; out1[oq*4+1] += v1*t4.y;
                        out1[oq*4+2] += v1*t4.z; out1[oq*4+3] += v1*t4.w;
                    }
                }
            }
        }
        size_t base0 = (((size_t)b*T + t0    )*NN + i0 + i)*FO + o0;
        size_t base1 = (((size_t)b*T + t0 + 1)*NN + i0 + i)*FO + o0;
#pragma unroll
        for (int oq = 0; oq < 4; oq++) {
            float4 v0, v1;
            v0.x = fmaxf(out0[oq*4+0], 0.f); v0.y = fmaxf(out0[oq*4+1], 0.f);
            v0.z = fmaxf(out0[oq*4+2], 0.f); v0.w = fmaxf(out0[oq*4+3], 0.f);
            v1.x = fmaxf(out1[oq*4+0], 0.f); v1.y = fmaxf(out1[oq*4+1], 0.f);
            v1.z = fmaxf(out1[oq*4+2], 0.f); v1.w = fmaxf(out1[oq*4+3], 0.f);
            *(float4*)(g_xgc + base0 + oq*4) = v0;
            *(float4*)(g_xgc + base1 + oq*4) = v1;
        }
    }
}

// ---------------- K7: temporal conv + residual conv + relu + layernorm ----------------
#define S7_WS   0
#define S7_XG   15232
#define S7_XR   (S7_XG + 6144)
#define S7_YB   (S7_XR + 1024)
#define S7_MU   (S7_YB + 2080)
#define S7_RI   (S7_MU + 32)
#define S7_TOTF (S7_RI + 32)

__global__ __launch_bounds__(256) void k7_final(
    const float* __restrict__ x,
    const float* __restrict__ tw, const float* __restrict__ tb,
    const float* __restrict__ rw, const float* __restrict__ rb,
    const float* __restrict__ lg, const float* __restrict__ lb,
    float* __restrict__ out)
{
    extern __shared__ float s7[];
    float* Ws = s7 + S7_WS;
    float* xg = s7 + S7_XG;
    float* xr = s7 + S7_XR;
    float* yb = s7 + S7_YB;
    float* mu = s7 + S7_MU;
    float* ri = s7 + S7_RI;

    int b = blockIdx.z, t = blockIdx.y, n0 = blockIdx.x << 5;
    int tid = threadIdx.x;

    for (int idx = tid; idx < FO*192; idx += 256) { int o = idx / 192, r = idx - o*192; Ws[r*68 + o] = tw[idx]; }
    for (int idx = tid; idx < FO*FI; idx += 256) { int o = idx >> 5, f = idx & 31; Ws[(192+f)*68 + o] = rw[idx]; }
#pragma unroll
    for (int dt = 0; dt < 3; dt++) {
        int ts = t + dt - 1;
        if (ts >= 0 && ts < T) {
            const float* src = g_xgc + (((size_t)b*T + ts)*NN + n0) * FO;
            for (int idx = tid; idx < 32*FO; idx += 256) xg[dt*2048 + idx] = src[idx];
        } else {
            for (int idx = tid; idx < 32*FO; idx += 256) xg[dt*2048 + idx] = 0.f;
        }
    }
    {
        const float* src = x + (((size_t)b*T + t)*NN + n0) * FI;
        for (int idx = tid; idx < 32*FI; idx += 256) xr[idx] = src[idx];
    }
    __syncthreads();

    int og = tid & 15, nlg = tid >> 4;
    int o0 = og << 2, nl0 = nlg << 1;
    float4 tb4 = *(const float4*)(tb + o0);
    float4 rb4 = *(const float4*)(rb + o0);
    float acc0[4], acc1[4];
#pragma unroll
    for (int c = 0; c < 4; c++) {
        float bia = ((const float*)&tb4)[c] + ((const float*)&rb4)[c];
        acc0[c] = bia; acc1[c] = bia;
    }

    for (int c = 0; c < FO; c++) {
#pragma unroll
        for (int dt = 0; dt < 3; dt++) {
            float4 w = *(const float4*)(Ws + (c*3 + dt)*68 + o0);
            float xa = xg[dt*2048 + nl0*FO + c];
            float xb2 = xg[dt*2048 + nl0*FO + FO + c];
            acc0[0] += xa*w.x;  acc0[1] += xa*w.y;  acc0[2] += xa*w.z;  acc0[3] += xa*w.w;
            acc1[0] += xb2*w.x; acc1[1] += xb2*w.y; acc1[2] += xb2*w.z; acc1[3] += xb2*w.w;
        }
    }
#pragma unroll
    for (int f = 0; f < FI; f++) {
        float4 w = *(const float4*)(Ws + (192 + f)*68 + o0);
        float xa = xr[nl0*FI + f];
        float xb2 = xr[nl0*FI + FI + f];
        acc0[0] += xa*w.x;  acc0[1] += xa*w.y;  acc0[2] += xa*w.z;  acc0[3] += xa*w.w;
        acc1[0] += xb2*w.x; acc1[1] += xb2*w.y; acc1[2] += xb2*w.z; acc1[3] += xb2*w.w;
    }
#pragma unroll
    for (int c = 0; c < 4; c++) {
        float v0 = acc0[c] > 0.f ? acc0[c] : 0.f;
        float v1 = acc1[c] > 0.f ? acc1[c] : 0.f;
        yb[nl0*65 + o0 + c] = v0;
        yb[(nl0+1)*65 + o0 + c] = v1;
    }
    __syncthreads();
    if (tid < 32) {
        float m = 0.f;
#pragma unroll
        for (int o = 0; o < FO; o++) m += yb[tid*65 + o];
        m *= (1.f/FO);
        float v = 0.f;
#pragma unroll
        for (int o = 0; o < FO; o++) { float d = yb[tid*65 + o] - m; v += d*d; }
        v *= (1.f/FO);
        mu[tid] = m;
        ri[tid] = rsqrtf(v + 1e-5f);
    }
    __syncthreads();
    float4 g4 = *(const float4*)(lg + o0);
    float4 b4 = *(const float4*)(lb + o0);
#pragma unroll
    for (int j = 0; j < 2; j++) {
        int nl = nl0 + j;
        float m = mu[nl], r = ri[nl];
        float4 ov;
        ov.x = (yb[nl*65 + o0 + 0] - m)*r*g4.x + b4.x;
        ov.y = (yb[nl*65 + o0 + 1] - m)*r*g4.y + b4.y;
        ov.z = (yb[nl*65 + o0 + 2] - m)*r*g4.z + b4.z;
        ov.w = (yb[nl*65 + o0 + 3] - m)*r*g4.w + b4.w;
        *(float4*)(out + ((((size_t)b*T + t)*NN + n0 + nl) << 6) + o0) = ov;
    }
}

// ---------------- launch ----------------
extern "C" void kernel_launch(void* const* d_in, const int* in_sizes, int n_in,
                              void* d_out, int out_size)
{
    const float* x     = (const float*)d_in[0];
    const float* cheb  = (const float*)d_in[1];
    const float* wq_t  = (const float*)d_in[2];
    const float* wk_t  = (const float*)d_in[3];
    const float* wq_s  = (const float*)d_in[4];
    const float* wk_s  = (const float*)d_in[5];
    const float* theta = (const float*)d_in[6];
    const float* tw    = (const float*)d_in[7];
    const float* tbv   = (const float*)d_in[8];
    const float* rw    = (const float*)d_in[9];
    const float* rbv   = (const float*)d_in[10];
    const float* lg    = (const float*)d_in[11];
    const float* lb    = (const float*)d_in[12];
    float* out = (float*)d_out;

    cudaFuncSetAttribute(k6_mma, cudaFuncAttributeMaxDynamicSharedMemorySize, K6_SMEM);
    cudaFuncSetAttribute(k7_final, cudaFuncAttributeMaxDynamicSharedMemorySize,
                         S7_TOTF * (int)sizeof(float));

    k1_qk<<<(B*T*NN)/256, 256>>>(x, wq_t, wk_t);
    k2_ta<<<B*T, 256>>>();
    k3_xta<<<dim3(NN/32, B), 1024>>>(x);
    k4_qk<<<(B*T*NN)/256, 256>>>(wq_s, wk_s);
    k5_sa<<<B*NN, 256>>>();
    k6_mma<<<dim3(T/2, NN/128, B), 512, K6_SMEM>>>(cheb, theta);
    k7_final<<<dim3(NN/32, T, B), 256, S7_TOTF * (int)sizeof(float)>>>(
        x, tw, tbv, rw, rbv, lg, lb, out);
}